// round 7
// baseline (speedup 1.0000x reference)
#include <cuda_runtime.h>
#include <cstdint>
#include <math_constants.h>

// Problem constants (shapes fixed by the dataset)
#define NCLS   64        // n
#define KSUP   5         // k
#define QPG    128       // q
#define DIM    256       // d
#define GROUP  (KSUP + QPG)   // 133
#define NQ     (NCLS * QPG)   // 8192
#define KNEIGH 10

// ---------------- scratch (device globals: allocation-free) ----------------
__device__ float g_qn[NQ * DIM];        // normalized queries      (8 MB)
__device__ float g_query[NQ * DIM];     // raw queries, contiguous (8 MB)
__device__ float g_proto[NCLS * DIM];
__device__ float g_pn[NCLS * DIM];      // normalized protos
__device__ float g_selfsim[NCLS];
__device__ float g_m[NCLS];
__device__ float g_preval[NQ];
__device__ int   g_prelabel[NQ];
__device__ float g_S[(size_t)NQ * NQ];  // query_sim (256 MB)
__device__ int   g_topidx[NQ * KNEIGH];
__device__ float g_ap[NCLS * DIM];      // adapted protos
__device__ float g_apn[NCLS * DIM];     // normalized adapted protos
__device__ float g_aq[NQ * DIM];        // adapted queries (8 MB)

// ---------------- helpers ----------------
__device__ __forceinline__ float block_reduce_sum_256(float v, float* sh8) {
    int t = threadIdx.x;
    #pragma unroll
    for (int o = 16; o > 0; o >>= 1) v += __shfl_down_sync(0xffffffffu, v, o);
    if ((t & 31) == 0) sh8[t >> 5] = v;
    __syncthreads();
    if (t < 8) {
        v = sh8[t];
        #pragma unroll
        for (int o = 4; o > 0; o >>= 1) v += __shfl_down_sync(0xffu, v, o);
        if (t == 0) sh8[0] = v;
    }
    __syncthreads();
    float r = sh8[0];
    __syncthreads();
    return r;
}

// ---------------- 1) prototypes: mean of support, normalize, self_sim ------
__global__ void proto_kernel(const float* __restrict__ x) {
    int b = blockIdx.x, t = threadIdx.x;
    __shared__ float sh8[8];
    float s = 0.f;
    #pragma unroll
    for (int i = 0; i < KSUP; i++)
        s += x[(size_t)(b * GROUP + i) * DIM + t];
    float p = s * (1.0f / KSUP);
    g_proto[b * DIM + t] = p;
    float ss = block_reduce_sum_256(p * p, sh8);
    float pn = p / sqrtf(ss);
    g_pn[b * DIM + t] = pn;
    float ss2 = block_reduce_sum_256(pn * pn, sh8);
    if (t == 0) g_selfsim[b] = ss2;
}

// ---------------- 2) queries: copy contiguous + normalize ------------------
__global__ void qnorm_kernel(const float* __restrict__ x) {
    int i = blockIdx.x, t = threadIdx.x;
    int g = i / QPG, qi = i - g * QPG;
    __shared__ float sh8[8];
    float v = x[(size_t)(g * GROUP + KSUP + qi) * DIM + t];
    g_query[(size_t)i * DIM + t] = v;
    float ss = block_reduce_sum_256(v * v, sh8);
    g_qn[(size_t)i * DIM + t] = v / sqrtf(ss);
}

// ---------------- 3) pre_sim + per-row argmax ------------------------------
__global__ void presim_kernel() {
    int i = blockIdx.x, t = threadIdx.x;
    __shared__ float q[DIM];
    __shared__ float sims[NCLS];
    q[t] = g_qn[(size_t)i * DIM + t];
    __syncthreads();
    int w = t >> 5, lane = t & 31;
    for (int c = w; c < NCLS; c += 8) {
        const float* p = g_pn + c * DIM;
        float s = 0.f;
        #pragma unroll
        for (int u = 0; u < DIM; u += 32) s += q[u + lane] * p[u + lane];
        #pragma unroll
        for (int o = 16; o > 0; o >>= 1) s += __shfl_down_sync(0xffffffffu, s, o);
        if (lane == 0) sims[c] = s;
    }
    __syncthreads();
    if (t == 0) {
        float best = -CUDART_INF_F; int bi = 0;
        #pragma unroll
        for (int c = 0; c < NCLS; c++)
            if (sims[c] > best) { best = sims[c]; bi = c; }
        g_preval[i] = best;
        g_prelabel[i] = bi;
    }
}

// ---------------- 4) per-class m = max(assigned sims, self_sim) ------------
__global__ void classmax_kernel() {
    int j = blockIdx.x, t = threadIdx.x;
    __shared__ float sh[256];
    float lm = -CUDART_INF_F;
    for (int i = t; i < NQ; i += 256)
        if (g_prelabel[i] == j) { float v = g_preval[i]; if (v > lm) lm = v; }
    sh[t] = lm;
    __syncthreads();
    for (int o = 128; o > 0; o >>= 1) {
        if (t < o) { if (sh[t + o] > sh[t]) sh[t] = sh[t + o]; }
        __syncthreads();
    }
    if (t == 0) {
        float m = sh[0];
        float ss = g_selfsim[j];
        g_m[j] = (ss > m) ? ss : m;
    }
}

// ---------------- 5) adapted prototypes ------------------------------------
__global__ void adaptproto_kernel() {
    int j = blockIdx.x, t = threadIdx.x;
    float m = g_m[j];
    float acc = 0.f, z = 0.f;
    for (int i = 0; i < NQ; i++) {
        if (g_prelabel[i] == j) {
            float w = expf(g_preval[i] - m);
            acc += w * g_query[(size_t)i * DIM + t];
            z += w;
        }
    }
    float es = expf(g_selfsim[j] - m);
    float Z = z + es;
    g_ap[j * DIM + t] = (acc + es * g_proto[j * DIM + t]) / Z;
}

// ---------------- 6) normalize adapted protos ------------------------------
__global__ void apnorm_kernel() {
    int j = blockIdx.x, t = threadIdx.x;
    __shared__ float sh8[8];
    float v = g_ap[j * DIM + t];
    float ss = block_reduce_sum_256(v * v, sh8);
    g_apn[j * DIM + t] = v / sqrtf(ss);
}

// ---------------- 7) S = Qn Qn^T  (symmetric, tiled SGEMM) -----------------
#define BM 128
#define BN 128
#define BK 16
__global__ __launch_bounds__(256) void simgemm_kernel() {
    int bx = blockIdx.x;  // col tile
    int by = blockIdx.y;  // row tile
    if (by > bx) return;  // upper triangle only; mirror-store below

    __shared__ float As[BK][BM];
    __shared__ float Bs[BK][BN];
    int tid = threadIdx.x;
    int tx = tid & 15, ty = tid >> 4;
    int rowBase = by * BM, colBase = bx * BN;

    float acc[8][8];
    #pragma unroll
    for (int i = 0; i < 8; i++)
        #pragma unroll
        for (int j = 0; j < 8; j++) acc[i][j] = 0.f;

    for (int kk = 0; kk < DIM; kk += BK) {
        #pragma unroll
        for (int l = 0; l < 2; l++) {
            int s = tid + l * 256;     // 0..511 float4 slots
            int r = s >> 2;            // 0..127
            int kc = (s & 3) * 4;      // 0,4,8,12
            float4 va = *(const float4*)&g_qn[(size_t)(rowBase + r) * DIM + kk + kc];
            As[kc + 0][r] = va.x; As[kc + 1][r] = va.y;
            As[kc + 2][r] = va.z; As[kc + 3][r] = va.w;
            float4 vb = *(const float4*)&g_qn[(size_t)(colBase + r) * DIM + kk + kc];
            Bs[kc + 0][r] = vb.x; Bs[kc + 1][r] = vb.y;
            Bs[kc + 2][r] = vb.z; Bs[kc + 3][r] = vb.w;
        }
        __syncthreads();
        #pragma unroll
        for (int k = 0; k < BK; k++) {
            float a[8], b[8];
            *(float4*)&a[0] = *(const float4*)&As[k][ty * 8];
            *(float4*)&a[4] = *(const float4*)&As[k][ty * 8 + 4];
            *(float4*)&b[0] = *(const float4*)&Bs[k][tx * 8];
            *(float4*)&b[4] = *(const float4*)&Bs[k][tx * 8 + 4];
            #pragma unroll
            for (int i = 0; i < 8; i++)
                #pragma unroll
                for (int j = 0; j < 8; j++)
                    acc[i][j] += a[i] * b[j];
        }
        __syncthreads();
    }

    // normal store
    #pragma unroll
    for (int i = 0; i < 8; i++) {
        size_t r = (size_t)(rowBase + ty * 8 + i);
        float4 v0 = make_float4(acc[i][0], acc[i][1], acc[i][2], acc[i][3]);
        float4 v1 = make_float4(acc[i][4], acc[i][5], acc[i][6], acc[i][7]);
        *(float4*)&g_S[r * NQ + colBase + tx * 8]     = v0;
        *(float4*)&g_S[r * NQ + colBase + tx * 8 + 4] = v1;
    }
    // mirrored (transposed) store
    if (bx != by) {
        #pragma unroll
        for (int j = 0; j < 8; j++) {
            size_t c = (size_t)(colBase + tx * 8 + j);
            float4 v0 = make_float4(acc[0][j], acc[1][j], acc[2][j], acc[3][j]);
            float4 v1 = make_float4(acc[4][j], acc[5][j], acc[6][j], acc[7][j]);
            *(float4*)&g_S[c * NQ + rowBase + ty * 8]     = v0;
            *(float4*)&g_S[c * NQ + rowBase + ty * 8 + 4] = v1;
        }
    }
}

// ---------------- 8) per-row top-10 ----------------------------------------
__global__ __launch_bounds__(256) void topk_kernel() {
    int i = blockIdx.x, t = threadIdx.x;
    const float* row = g_S + (size_t)i * NQ;

    float tv[KNEIGH]; int ti[KNEIGH];
    #pragma unroll
    for (int c = 0; c < KNEIGH; c++) { tv[c] = -CUDART_INF_F; ti[c] = -1; }

    for (int j = t; j < NQ; j += 256) {
        float s = row[j];
        if (s > tv[KNEIGH - 1]) {
            int jj = j;
            #pragma unroll
            for (int c = 0; c < KNEIGH; c++) {
                if (s > tv[c]) {
                    float pv = tv[c]; int pi = ti[c];
                    tv[c] = s; ti[c] = jj;
                    s = pv; jj = pi;
                }
            }
        }
    }

    __shared__ float cv[256][KNEIGH];
    __shared__ int   ci[256][KNEIGH];
    __shared__ float rv[256];
    __shared__ int   ri[256];
    __shared__ int   rt[256];
    #pragma unroll
    for (int c = 0; c < KNEIGH; c++) { cv[t][c] = tv[c]; ci[t][c] = ti[c]; }
    __syncthreads();

    int p = 0;
    for (int r = 0; r < KNEIGH; r++) {
        rv[t] = (p < KNEIGH) ? cv[t][p] : -CUDART_INF_F;
        ri[t] = (p < KNEIGH) ? ci[t][p] : -1;
        rt[t] = t;
        __syncthreads();
        for (int o = 128; o > 0; o >>= 1) {
            if (t < o) {
                if (rv[t + o] > rv[t]) {
                    rv[t] = rv[t + o]; ri[t] = ri[t + o]; rt[t] = rt[t + o];
                }
            }
            __syncthreads();
        }
        if (t == 0) g_topidx[i * KNEIGH + r] = ri[0];
        int win = rt[0];
        __syncthreads();
        if (t == win) p++;
    }
}

// ---------------- 9) mutual kNN softmax + adapted queries ------------------
__global__ void mutual_kernel() {
    int i = blockIdx.x, t = threadIdx.x;
    __shared__ int   nidx[KNEIGH];
    __shared__ float wgt[KNEIGH];
    if (t < KNEIGH) nidx[t] = g_topidx[i * KNEIGH + t];
    __syncthreads();
    if (t < KNEIGH) {
        int jn = nidx[t];
        bool mut = false;
        #pragma unroll
        for (int c = 0; c < KNEIGH; c++)
            if (g_topidx[jn * KNEIGH + c] == i) mut = true;
        wgt[t] = mut ? g_S[(size_t)i * NQ + jn] : -CUDART_INF_F;
    }
    __syncthreads();
    if (t == 0) {
        float m = -CUDART_INF_F;
        #pragma unroll
        for (int c = 0; c < KNEIGH; c++) if (wgt[c] > m) m = wgt[c];
        float sum = 0.f;
        float e[KNEIGH];
        #pragma unroll
        for (int c = 0; c < KNEIGH; c++) { e[c] = expf(wgt[c] - m); sum += e[c]; }
        float inv = 1.0f / sum;
        #pragma unroll
        for (int c = 0; c < KNEIGH; c++) wgt[c] = e[c] * inv;
    }
    __syncthreads();
    float acc = 0.f;
    #pragma unroll
    for (int c = 0; c < KNEIGH; c++) {
        float w = wgt[c];
        if (w != 0.f) acc += w * g_query[(size_t)nidx[c] * DIM + t];
    }
    g_aq[(size_t)i * DIM + t] = acc;
}

// ---------------- 10) final: tao * cos(adapted_query, adapted_proto) -------
__global__ void final_kernel(const float* __restrict__ tao, float* __restrict__ out) {
    int i = blockIdx.x, t = threadIdx.x;
    __shared__ float sh8[8];
    __shared__ float q[DIM];
    float v = g_aq[(size_t)i * DIM + t];
    float ss = block_reduce_sum_256(v * v, sh8);
    q[t] = v / sqrtf(ss);
    __syncthreads();
    int w = t >> 5, lane = t & 31;
    float tv = tao[0];
    for (int c = w; c < NCLS; c += 8) {
        const float* p = g_apn + c * DIM;
        float s = 0.f;
        #pragma unroll
        for (int u = 0; u < DIM; u += 32) s += q[u + lane] * p[u + lane];
        #pragma unroll
        for (int o = 16; o > 0; o >>= 1) s += __shfl_down_sync(0xffffffffu, s, o);
        if (lane == 0) out[(size_t)i * NCLS + c] = tv * s;
    }
}

// ---------------- launch ----------------------------------------------------
extern "C" void kernel_launch(void* const* d_in, const int* in_sizes, int n_in,
                              void* d_out, int out_size) {
    const float* x   = (const float*)d_in[0];
    const float* tao = (const float*)d_in[1];
    float* out = (float*)d_out;

    proto_kernel<<<NCLS, 256>>>(x);
    qnorm_kernel<<<NQ, 256>>>(x);
    presim_kernel<<<NQ, 256>>>();
    classmax_kernel<<<NCLS, 256>>>();
    adaptproto_kernel<<<NCLS, 256>>>();
    apnorm_kernel<<<NCLS, 256>>>();
    simgemm_kernel<<<dim3(NQ / BN, NQ / BM), 256>>>();
    topk_kernel<<<NQ, 256>>>();
    mutual_kernel<<<NQ, 256>>>();
    final_kernel<<<NQ, 256>>>(tao, out);
}

// round 15
// speedup vs baseline: 1.6605x; 1.6605x over previous
#include <cuda_runtime.h>
#include <cuda_bf16.h>
#include <cstdint>
#include <math_constants.h>

// Problem constants
#define NCLS   64
#define KSUP   5
#define QPG    128
#define DIM    256
#define GROUP  (KSUP + QPG)   // 133
#define NQ     (NCLS * QPG)   // 8192
#define KNEIGH 10

// ---------------- scratch (device globals) ----------------
__device__ float g_query[NQ * DIM];                       // raw queries (8 MB)
__device__ __align__(16) __nv_bfloat16 g_q0[NQ * DIM];    // bf16 split hi
__device__ __align__(16) __nv_bfloat16 g_q1[NQ * DIM];    // bf16 split mid
__device__ __align__(16) __nv_bfloat16 g_q2[NQ * DIM];    // bf16 split lo
__device__ float g_proto[NCLS * DIM];
__device__ float g_pn[NCLS * DIM];
__device__ float g_selfsim[NCLS];
__device__ unsigned g_mbits[NCLS];
__device__ float g_preval[NQ];
__device__ int   g_prelabel[NQ];
__device__ float g_S[(size_t)NQ * NQ];                    // 256 MB
__device__ int   g_topidx[NQ * KNEIGH];
__device__ float g_ap[NCLS * DIM];
__device__ float g_apn[NCLS * DIM];
__device__ float g_aq[NQ * DIM];

// ---------------- helpers ----------------
__device__ __forceinline__ uint32_t smem_u32(const void* p) {
    uint32_t a;
    asm("{ .reg .u64 t; cvta.to.shared.u64 t, %1; cvt.u32.u64 %0, t; }"
        : "=r"(a) : "l"(p));
    return a;
}
__device__ __forceinline__ void ldm_x4(uint32_t& r0, uint32_t& r1,
                                       uint32_t& r2, uint32_t& r3, uint32_t addr) {
    asm volatile("ldmatrix.sync.aligned.m8n8.x4.shared.b16 {%0,%1,%2,%3}, [%4];"
                 : "=r"(r0), "=r"(r1), "=r"(r2), "=r"(r3) : "r"(addr));
}
__device__ __forceinline__ void mma_bf16(float* c, const uint32_t* a, const uint32_t* b) {
    asm volatile(
        "mma.sync.aligned.m16n8k16.row.col.f32.bf16.bf16.f32 "
        "{%0,%1,%2,%3}, {%4,%5,%6,%7}, {%8,%9}, {%0,%1,%2,%3};"
        : "+f"(c[0]), "+f"(c[1]), "+f"(c[2]), "+f"(c[3])
        : "r"(a[0]), "r"(a[1]), "r"(a[2]), "r"(a[3]), "r"(b[0]), "r"(b[1]));
}

// ordered-uint encode/decode for float atomicMax
__device__ __forceinline__ unsigned fenc(float f) {
    unsigned u = __float_as_uint(f);
    return (u >> 31) ? ~u : (u | 0x80000000u);
}
__device__ __forceinline__ float fdec(unsigned u) {
    return (u & 0x80000000u) ? __uint_as_float(u & 0x7fffffffu) : __uint_as_float(~u);
}

__device__ __forceinline__ float block_reduce_sum_256(float v, float* sh8) {
    int t = threadIdx.x;
    #pragma unroll
    for (int o = 16; o > 0; o >>= 1) v += __shfl_down_sync(0xffffffffu, v, o);
    if ((t & 31) == 0) sh8[t >> 5] = v;
    __syncthreads();
    if (t < 8) {
        v = sh8[t];
        #pragma unroll
        for (int o = 4; o > 0; o >>= 1) v += __shfl_down_sync(0xffu, v, o);
        if (t == 0) sh8[0] = v;
    }
    __syncthreads();
    float r = sh8[0];
    __syncthreads();
    return r;
}

// ---------------- 1) prototypes ----------------
__global__ void proto_kernel(const float* __restrict__ x) {
    int b = blockIdx.x, t = threadIdx.x;
    __shared__ float sh8[8];
    float s = 0.f;
    #pragma unroll
    for (int i = 0; i < KSUP; i++)
        s += x[(size_t)(b * GROUP + i) * DIM + t];
    float p = s * (1.0f / KSUP);
    g_proto[b * DIM + t] = p;
    float ss = block_reduce_sum_256(p * p, sh8);
    float pn = p / sqrtf(ss);
    g_pn[b * DIM + t] = pn;
    float ss2 = block_reduce_sum_256(pn * pn, sh8);
    if (t == 0) {
        g_selfsim[b] = ss2;
        g_mbits[b] = fenc(-CUDART_INF_F);
    }
}

// ---------------- 2) fused qnorm + bf16 split + presim + class max ---------
__global__ void qnorm_presim_kernel(const float* __restrict__ x) {
    int i = blockIdx.x, t = threadIdx.x;
    int g = i / QPG, qi = i - g * QPG;
    __shared__ float sh8[8];
    __shared__ float q[DIM];
    __shared__ float sims[NCLS];
    float v = x[(size_t)(g * GROUP + KSUP + qi) * DIM + t];
    g_query[(size_t)i * DIM + t] = v;
    float ss = block_reduce_sum_256(v * v, sh8);
    float qn = v / sqrtf(ss);
    q[t] = qn;
    __nv_bfloat16 b0 = __float2bfloat16(qn);
    float r1 = qn - __bfloat162float(b0);
    __nv_bfloat16 b1 = __float2bfloat16(r1);
    float r2 = r1 - __bfloat162float(b1);
    __nv_bfloat16 b2 = __float2bfloat16(r2);
    size_t off = (size_t)i * DIM + t;
    g_q0[off] = b0; g_q1[off] = b1; g_q2[off] = b2;
    __syncthreads();
    int w = t >> 5, lane = t & 31;
    for (int c = w; c < NCLS; c += 8) {
        const float* p = g_pn + c * DIM;
        float s = 0.f;
        #pragma unroll
        for (int u = 0; u < DIM; u += 32) s += q[u + lane] * p[u + lane];
        #pragma unroll
        for (int o = 16; o > 0; o >>= 1) s += __shfl_down_sync(0xffffffffu, s, o);
        if (lane == 0) sims[c] = s;
    }
    __syncthreads();
    if (t == 0) {
        float best = -CUDART_INF_F; int bi = 0;
        #pragma unroll
        for (int c = 0; c < NCLS; c++)
            if (sims[c] > best) { best = sims[c]; bi = c; }
        g_preval[i] = best;
        g_prelabel[i] = bi;
        atomicMax(&g_mbits[bi], fenc(best));
    }
}

// ---------------- 3) adapted prototypes (warp-parallel ballot scan) --------
__global__ void adaptproto_kernel() {
    int j = blockIdx.x, t = threadIdx.x;
    int w = t >> 5, l = t & 31;
    __shared__ float sacc[8][DIM];
    __shared__ float sz[8];
    float m = fmaxf(fdec(g_mbits[j]), g_selfsim[j]);
    float acc[8];
    #pragma unroll
    for (int jj = 0; jj < 8; jj++) acc[jj] = 0.f;
    float z = 0.f;
    int base0 = w * (NQ / 8);
    for (int base = base0; base < base0 + NQ / 8; base += 32) {
        int i = base + l;
        int lab = g_prelabel[i];
        float pv = g_preval[i];
        unsigned mask = __ballot_sync(0xffffffffu, lab == j);
        while (mask) {
            int b = __ffs(mask) - 1;
            mask &= mask - 1;
            int ib = base + b;
            float wv = __shfl_sync(0xffffffffu, pv, b);
            float e = expf(wv - m);
            if (l == 0) z += e;
            const float* row = g_query + (size_t)ib * DIM;
            #pragma unroll
            for (int jj = 0; jj < 8; jj++) acc[jj] += e * row[l + 32 * jj];
        }
    }
    #pragma unroll
    for (int jj = 0; jj < 8; jj++) sacc[w][l + 32 * jj] = acc[jj];
    if (l == 0) sz[w] = z;
    __syncthreads();
    float a = 0.f, Z = 0.f;
    #pragma unroll
    for (int ww = 0; ww < 8; ww++) { a += sacc[ww][t]; Z += sz[ww]; }
    float es = expf(g_selfsim[j] - m);
    Z += es;
    g_ap[j * DIM + t] = (a + es * g_proto[j * DIM + t]) / Z;
}

// ---------------- 4) normalize adapted protos ------------------------------
__global__ void apnorm_kernel() {
    int j = blockIdx.x, t = threadIdx.x;
    __shared__ float sh8[8];
    float v = g_ap[j * DIM + t];
    float ss = block_reduce_sum_256(v * v, sh8);
    g_apn[j * DIM + t] = v / sqrtf(ss);
}

// ---------------- 5) S = Qn Qn^T via mma.sync bf16 (6-pass split) ----------
// 128x128 CTA tile, 8 warps (2 m x 4 n), warp tile 64x32.
// smem: 6 staged operand tiles [128 rows][32 k] bf16, rows padded to 80 B.
#define PADB 80
#define BUFSZ (128 * PADB)                 // 10240 B
#define GEMM_SMEM (6 * BUFSZ)              // 61440 B

__global__ __launch_bounds__(256, 2) void simgemm_mma_kernel() {
    int bx = blockIdx.x, by = blockIdx.y;
    if (by > bx) return;                    // symmetric: upper triangle only
    extern __shared__ __align__(16) char sm[];
    uint32_t sb = smem_u32(sm);
    int tid = threadIdx.x, l = tid & 31, wid = tid >> 5;
    int wm = wid & 1, wn = wid >> 1;        // 2 x 4 warp grid
    int rowBase = by * 128, colBase = bx * 128;

    float acc[4][4][4];
    #pragma unroll
    for (int mt = 0; mt < 4; mt++)
        #pragma unroll
        for (int nt = 0; nt < 4; nt++)
            #pragma unroll
            for (int e = 0; e < 4; e++) acc[mt][nt][e] = 0.f;

    // ldmatrix per-lane addressing (same pattern for A and B frags)
    int subrow = ((l >> 3) & 1) * 8 + (l & 7);
    int khalfB = (l >> 4) * 16;             // byte offset of k-half

    const uint4* q4[3] = { (const uint4*)g_q0, (const uint4*)g_q1, (const uint4*)g_q2 };

    for (int kk = 0; kk < DIM; kk += 32) {
        __syncthreads();
        int kw = kk >> 3;                   // uint4 column base
        #pragma unroll
        for (int it = 0; it < 2; it++) {
            int idx = tid + it * 256;       // 0..511
            int row = idx >> 2, c = idx & 3;
            int so = row * PADB + c * 16;
            #pragma unroll
            for (int sp = 0; sp < 3; sp++) {
                *(uint4*)(sm + sp * BUFSZ + so) =
                    q4[sp][(size_t)(rowBase + row) * 32 + kw + c];
                *(uint4*)(sm + (3 + sp) * BUFSZ + so) =
                    q4[sp][(size_t)(colBase + row) * 32 + kw + c];
            }
        }
        __syncthreads();
        #pragma unroll
        for (int ks = 0; ks < 2; ks++) {
            int kb = ks * 32 + khalfB;
            // B fragments for all 3 splits: b[split][nt][2]
            uint32_t bf[3][4][2];
            #pragma unroll
            for (int sp = 0; sp < 3; sp++) {
                #pragma unroll
                for (int nt2 = 0; nt2 < 2; nt2++) {
                    uint32_t r0, r1, r2, r3;
                    uint32_t ad = sb + (3 + sp) * BUFSZ
                                + (wn * 32 + nt2 * 16 + subrow) * PADB + kb;
                    ldm_x4(r0, r1, r2, r3, ad);
                    bf[sp][nt2 * 2][0]     = r0; bf[sp][nt2 * 2][1]     = r2;
                    bf[sp][nt2 * 2 + 1][0] = r1; bf[sp][nt2 * 2 + 1][1] = r3;
                }
            }
            #pragma unroll
            for (int mt = 0; mt < 4; mt++) {
                uint32_t a[4];
                uint32_t abase = (wm * 64 + mt * 16 + subrow) * PADB + kb;
                // A0 x {B0, B1, B2}
                ldm_x4(a[0], a[1], a[2], a[3], sb + 0 * BUFSZ + abase);
                #pragma unroll
                for (int nt = 0; nt < 4; nt++) {
                    mma_bf16(acc[mt][nt], a, bf[0][nt]);
                    mma_bf16(acc[mt][nt], a, bf[1][nt]);
                    mma_bf16(acc[mt][nt], a, bf[2][nt]);
                }
                // A1 x {B0, B1}
                ldm_x4(a[0], a[1], a[2], a[3], sb + 1 * BUFSZ + abase);
                #pragma unroll
                for (int nt = 0; nt < 4; nt++) {
                    mma_bf16(acc[mt][nt], a, bf[0][nt]);
                    mma_bf16(acc[mt][nt], a, bf[1][nt]);
                }
                // A2 x {B0}
                ldm_x4(a[0], a[1], a[2], a[3], sb + 2 * BUFSZ + abase);
                #pragma unroll
                for (int nt = 0; nt < 4; nt++)
                    mma_bf16(acc[mt][nt], a, bf[0][nt]);
            }
        }
    }

    // direct store (c frag: rows t/4, t/4+8; cols (t&3)*2, +1)
    int fr = l >> 2, fc = (l & 3) * 2;
    #pragma unroll
    for (int mt = 0; mt < 4; mt++) {
        #pragma unroll
        for (int nt = 0; nt < 4; nt++) {
            size_t r0 = (size_t)(rowBase + wm * 64 + mt * 16 + fr);
            int c0 = colBase + wn * 32 + nt * 8 + fc;
            *(float2*)&g_S[r0 * NQ + c0] = make_float2(acc[mt][nt][0], acc[mt][nt][1]);
            *(float2*)&g_S[(r0 + 8) * NQ + c0] = make_float2(acc[mt][nt][2], acc[mt][nt][3]);
        }
    }

    // mirrored store via smem transpose (coalesced), two 64-col halves
    if (bx != by) {
        float* st = (float*)sm;             // [64][132] floats = 33792 B
        #pragma unroll
        for (int h = 0; h < 2; h++) {
            __syncthreads();
            if ((wn >> 1) == h) {
                #pragma unroll
                for (int mt = 0; mt < 4; mt++) {
                    int lrow = wm * 64 + mt * 16 + fr;
                    #pragma unroll
                    for (int nt = 0; nt < 4; nt++) {
                        int cl = (wn & 1) * 32 + nt * 8 + fc;
                        st[cl * 132 + lrow]           = acc[mt][nt][0];
                        st[(cl + 1) * 132 + lrow]     = acc[mt][nt][1];
                        st[cl * 132 + lrow + 8]       = acc[mt][nt][2];
                        st[(cl + 1) * 132 + lrow + 8] = acc[mt][nt][3];
                    }
                }
            }
            __syncthreads();
            #pragma unroll
            for (int it = 0; it < 8; it++) {
                int idx = tid + it * 256;
                int r = idx >> 5, cq = idx & 31;
                float4 v = *(float4*)&st[r * 132 + cq * 4];
                *(float4*)&g_S[(size_t)(colBase + h * 64 + r) * NQ + rowBase + cq * 4] = v;
            }
        }
    }
}

// ---------------- 6) per-row top-10 ----------------------------------------
__global__ __launch_bounds__(256) void topk_kernel() {
    int i = blockIdx.x, t = threadIdx.x;
    const float* row = g_S + (size_t)i * NQ;

    float tv[KNEIGH]; int ti[KNEIGH];
    #pragma unroll
    for (int c = 0; c < KNEIGH; c++) { tv[c] = -CUDART_INF_F; ti[c] = -1; }

    for (int j = t; j < NQ; j += 256) {
        float s = row[j];
        if (s > tv[KNEIGH - 1]) {
            int jj = j;
            #pragma unroll
            for (int c = 0; c < KNEIGH; c++) {
                if (s > tv[c]) {
                    float pv = tv[c]; int pi = ti[c];
                    tv[c] = s; ti[c] = jj;
                    s = pv; jj = pi;
                }
            }
        }
    }

    __shared__ float cv[256][KNEIGH];
    __shared__ int   ci[256][KNEIGH];
    __shared__ float rv[256];
    __shared__ int   ri[256];
    __shared__ int   rt[256];
    #pragma unroll
    for (int c = 0; c < KNEIGH; c++) { cv[t][c] = tv[c]; ci[t][c] = ti[c]; }
    __syncthreads();

    int p = 0;
    for (int r = 0; r < KNEIGH; r++) {
        rv[t] = (p < KNEIGH) ? cv[t][p] : -CUDART_INF_F;
        ri[t] = (p < KNEIGH) ? ci[t][p] : -1;
        rt[t] = t;
        __syncthreads();
        for (int o = 128; o > 0; o >>= 1) {
            if (t < o) {
                if (rv[t + o] > rv[t]) {
                    rv[t] = rv[t + o]; ri[t] = ri[t + o]; rt[t] = rt[t + o];
                }
            }
            __syncthreads();
        }
        if (t == 0) g_topidx[i * KNEIGH + r] = ri[0];
        int win = rt[0];
        __syncthreads();
        if (t == win) p++;
    }
}

// ---------------- 7) mutual kNN softmax + adapted queries ------------------
__global__ void mutual_kernel() {
    int i = blockIdx.x, t = threadIdx.x;
    __shared__ int   nidx[KNEIGH];
    __shared__ float wgt[KNEIGH];
    if (t < KNEIGH) nidx[t] = g_topidx[i * KNEIGH + t];
    __syncthreads();
    if (t < KNEIGH) {
        int jn = nidx[t];
        bool mut = false;
        #pragma unroll
        for (int c = 0; c < KNEIGH; c++)
            if (g_topidx[jn * KNEIGH + c] == i) mut = true;
        wgt[t] = mut ? g_S[(size_t)i * NQ + jn] : -CUDART_INF_F;
    }
    __syncthreads();
    if (t == 0) {
        float m = -CUDART_INF_F;
        #pragma unroll
        for (int c = 0; c < KNEIGH; c++) if (wgt[c] > m) m = wgt[c];
        float sum = 0.f;
        float e[KNEIGH];
        #pragma unroll
        for (int c = 0; c < KNEIGH; c++) { e[c] = expf(wgt[c] - m); sum += e[c]; }
        float inv = 1.0f / sum;
        #pragma unroll
        for (int c = 0; c < KNEIGH; c++) wgt[c] = e[c] * inv;
    }
    __syncthreads();
    float acc = 0.f;
    #pragma unroll
    for (int c = 0; c < KNEIGH; c++) {
        float w = wgt[c];
        if (w != 0.f) acc += w * g_query[(size_t)nidx[c] * DIM + t];
    }
    g_aq[(size_t)i * DIM + t] = acc;
}

// ---------------- 8) final: tao * cos(adapted_query, adapted_proto) --------
__global__ void final_kernel(const float* __restrict__ tao, float* __restrict__ out) {
    int i = blockIdx.x, t = threadIdx.x;
    __shared__ float sh8[8];
    __shared__ float q[DIM];
    float v = g_aq[(size_t)i * DIM + t];
    float ss = block_reduce_sum_256(v * v, sh8);
    q[t] = v / sqrtf(ss);
    __syncthreads();
    int w = t >> 5, lane = t & 31;
    float tv = tao[0];
    for (int c = w; c < NCLS; c += 8) {
        const float* p = g_apn + c * DIM;
        float s = 0.f;
        #pragma unroll
        for (int u = 0; u < DIM; u += 32) s += q[u + lane] * p[u + lane];
        #pragma unroll
        for (int o = 16; o > 0; o >>= 1) s += __shfl_down_sync(0xffffffffu, s, o);
        if (lane == 0) out[(size_t)i * NCLS + c] = tv * s;
    }
}

// ---------------- launch ----------------------------------------------------
extern "C" void kernel_launch(void* const* d_in, const int* in_sizes, int n_in,
                              void* d_out, int out_size) {
    const float* x   = (const float*)d_in[0];
    const float* tao = (const float*)d_in[1];
    float* out = (float*)d_out;

    cudaFuncSetAttribute(simgemm_mma_kernel,
                         cudaFuncAttributeMaxDynamicSharedMemorySize, GEMM_SMEM);

    proto_kernel<<<NCLS, 256>>>(x);
    qnorm_presim_kernel<<<NQ, 256>>>(x);
    adaptproto_kernel<<<NCLS, 256>>>();
    apnorm_kernel<<<NCLS, 256>>>();
    simgemm_mma_kernel<<<dim3(NQ / 128, NQ / 128), 256, GEMM_SMEM>>>();
    topk_kernel<<<NQ, 256>>>();
    mutual_kernel<<<NQ, 256>>>();
    final_kernel<<<NQ, 256>>>(tao, out);
}

// round 16
// speedup vs baseline: 1.6643x; 1.0022x over previous
#include <cuda_runtime.h>
#include <cuda_bf16.h>
#include <cstdint>
#include <math_constants.h>

// Problem constants
#define NCLS   64
#define KSUP   5
#define QPG    128
#define DIM    256
#define GROUP  (KSUP + QPG)   // 133
#define NQ     (NCLS * QPG)   // 8192
#define KNEIGH 10

// ---------------- scratch (device globals) ----------------
__device__ float g_query[NQ * DIM];                       // raw queries (8 MB)
__device__ __align__(16) __nv_bfloat16 g_q0[NQ * DIM];    // bf16 split hi
__device__ __align__(16) __nv_bfloat16 g_q1[NQ * DIM];    // bf16 split mid
__device__ __align__(16) __nv_bfloat16 g_q2[NQ * DIM];    // bf16 split lo
__device__ float g_proto[NCLS * DIM];
__device__ float g_pn[NCLS * DIM];
__device__ float g_selfsim[NCLS];
__device__ unsigned g_mbits[NCLS];
__device__ float g_preval[NQ];
__device__ int   g_prelabel[NQ];
__device__ float g_S[(size_t)NQ * NQ];                    // 256 MB
__device__ int   g_topidx[NQ * KNEIGH];
__device__ float g_ap[NCLS * DIM];
__device__ float g_apn[NCLS * DIM];
__device__ float g_aq[NQ * DIM];

// ---------------- helpers ----------------
__device__ __forceinline__ uint32_t smem_u32(const void* p) {
    uint32_t a;
    asm("{ .reg .u64 t; cvta.to.shared.u64 t, %1; cvt.u32.u64 %0, t; }"
        : "=r"(a) : "l"(p));
    return a;
}
__device__ __forceinline__ void ldm_x4(uint32_t& r0, uint32_t& r1,
                                       uint32_t& r2, uint32_t& r3, uint32_t addr) {
    asm volatile("ldmatrix.sync.aligned.m8n8.x4.shared.b16 {%0,%1,%2,%3}, [%4];"
                 : "=r"(r0), "=r"(r1), "=r"(r2), "=r"(r3) : "r"(addr));
}
__device__ __forceinline__ void mma_bf16(float* c, const uint32_t* a, const uint32_t* b) {
    asm volatile(
        "mma.sync.aligned.m16n8k16.row.col.f32.bf16.bf16.f32 "
        "{%0,%1,%2,%3}, {%4,%5,%6,%7}, {%8,%9}, {%0,%1,%2,%3};"
        : "+f"(c[0]), "+f"(c[1]), "+f"(c[2]), "+f"(c[3])
        : "r"(a[0]), "r"(a[1]), "r"(a[2]), "r"(a[3]), "r"(b[0]), "r"(b[1]));
}

// ordered-uint encode/decode for float atomicMax
__device__ __forceinline__ unsigned fenc(float f) {
    unsigned u = __float_as_uint(f);
    return (u >> 31) ? ~u : (u | 0x80000000u);
}
__device__ __forceinline__ float fdec(unsigned u) {
    return (u & 0x80000000u) ? __uint_as_float(u & 0x7fffffffu) : __uint_as_float(~u);
}

__device__ __forceinline__ float block_reduce_sum_256(float v, float* sh8) {
    int t = threadIdx.x;
    #pragma unroll
    for (int o = 16; o > 0; o >>= 1) v += __shfl_down_sync(0xffffffffu, v, o);
    if ((t & 31) == 0) sh8[t >> 5] = v;
    __syncthreads();
    if (t < 8) {
        v = sh8[t];
        #pragma unroll
        for (int o = 4; o > 0; o >>= 1) v += __shfl_down_sync(0xffu, v, o);
        if (t == 0) sh8[0] = v;
    }
    __syncthreads();
    float r = sh8[0];
    __syncthreads();
    return r;
}

// ---------------- 1) prototypes ----------------
__global__ void proto_kernel(const float* __restrict__ x) {
    int b = blockIdx.x, t = threadIdx.x;
    __shared__ float sh8[8];
    float s = 0.f;
    #pragma unroll
    for (int i = 0; i < KSUP; i++)
        s += x[(size_t)(b * GROUP + i) * DIM + t];
    float p = s * (1.0f / KSUP);
    g_proto[b * DIM + t] = p;
    float ss = block_reduce_sum_256(p * p, sh8);
    float pn = p / sqrtf(ss);
    g_pn[b * DIM + t] = pn;
    float ss2 = block_reduce_sum_256(pn * pn, sh8);
    if (t == 0) {
        g_selfsim[b] = ss2;
        g_mbits[b] = fenc(-CUDART_INF_F);
    }
}

// ---------------- 2) fused qnorm + bf16 split + presim + class max ---------
__global__ void qnorm_presim_kernel(const float* __restrict__ x) {
    int i = blockIdx.x, t = threadIdx.x;
    int g = i / QPG, qi = i - g * QPG;
    __shared__ float sh8[8];
    __shared__ float q[DIM];
    __shared__ float sims[NCLS];
    float v = x[(size_t)(g * GROUP + KSUP + qi) * DIM + t];
    g_query[(size_t)i * DIM + t] = v;
    float ss = block_reduce_sum_256(v * v, sh8);
    float qn = v / sqrtf(ss);
    q[t] = qn;
    __nv_bfloat16 b0 = __float2bfloat16(qn);
    float r1 = qn - __bfloat162float(b0);
    __nv_bfloat16 b1 = __float2bfloat16(r1);
    float r2 = r1 - __bfloat162float(b1);
    __nv_bfloat16 b2 = __float2bfloat16(r2);
    size_t off = (size_t)i * DIM + t;
    g_q0[off] = b0; g_q1[off] = b1; g_q2[off] = b2;
    __syncthreads();
    int w = t >> 5, lane = t & 31;
    for (int c = w; c < NCLS; c += 8) {
        const float* p = g_pn + c * DIM;
        float s = 0.f;
        #pragma unroll
        for (int u = 0; u < DIM; u += 32) s += q[u + lane] * p[u + lane];
        #pragma unroll
        for (int o = 16; o > 0; o >>= 1) s += __shfl_down_sync(0xffffffffu, s, o);
        if (lane == 0) sims[c] = s;
    }
    __syncthreads();
    if (t == 0) {
        float best = -CUDART_INF_F; int bi = 0;
        #pragma unroll
        for (int c = 0; c < NCLS; c++)
            if (sims[c] > best) { best = sims[c]; bi = c; }
        g_preval[i] = best;
        g_prelabel[i] = bi;
        atomicMax(&g_mbits[bi], fenc(best));
    }
}

// ---------------- 3) adapted prototypes (warp-parallel ballot scan) --------
__global__ void adaptproto_kernel() {
    int j = blockIdx.x, t = threadIdx.x;
    int w = t >> 5, l = t & 31;
    __shared__ float sacc[8][DIM];
    __shared__ float sz[8];
    float m = fmaxf(fdec(g_mbits[j]), g_selfsim[j]);
    float acc[8];
    #pragma unroll
    for (int jj = 0; jj < 8; jj++) acc[jj] = 0.f;
    float z = 0.f;
    int base0 = w * (NQ / 8);
    for (int base = base0; base < base0 + NQ / 8; base += 32) {
        int i = base + l;
        int lab = g_prelabel[i];
        float pv = g_preval[i];
        unsigned mask = __ballot_sync(0xffffffffu, lab == j);
        while (mask) {
            int b = __ffs(mask) - 1;
            mask &= mask - 1;
            int ib = base + b;
            float wv = __shfl_sync(0xffffffffu, pv, b);
            float e = expf(wv - m);
            if (l == 0) z += e;
            const float* row = g_query + (size_t)ib * DIM;
            #pragma unroll
            for (int jj = 0; jj < 8; jj++) acc[jj] += e * row[l + 32 * jj];
        }
    }
    #pragma unroll
    for (int jj = 0; jj < 8; jj++) sacc[w][l + 32 * jj] = acc[jj];
    if (l == 0) sz[w] = z;
    __syncthreads();
    float a = 0.f, Z = 0.f;
    #pragma unroll
    for (int ww = 0; ww < 8; ww++) { a += sacc[ww][t]; Z += sz[ww]; }
    float es = expf(g_selfsim[j] - m);
    Z += es;
    g_ap[j * DIM + t] = (a + es * g_proto[j * DIM + t]) / Z;
}

// ---------------- 4) normalize adapted protos ------------------------------
__global__ void apnorm_kernel() {
    int j = blockIdx.x, t = threadIdx.x;
    __shared__ float sh8[8];
    float v = g_ap[j * DIM + t];
    float ss = block_reduce_sum_256(v * v, sh8);
    g_apn[j * DIM + t] = v / sqrtf(ss);
}

// ---------------- 5) S = Qn Qn^T via mma.sync bf16 (6-pass split) ----------
// 128x128 CTA tile, 8 warps (2 m x 4 n), warp tile 64x32.
// smem: 6 staged operand tiles [128 rows][32 k] bf16, rows padded to 80 B.
#define PADB 80
#define BUFSZ (128 * PADB)                 // 10240 B
#define GEMM_SMEM (6 * BUFSZ)              // 61440 B

__global__ __launch_bounds__(256, 2) void simgemm_mma_kernel() {
    int bx = blockIdx.x, by = blockIdx.y;
    if (by > bx) return;                    // symmetric: upper triangle only
    extern __shared__ __align__(16) char sm[];
    uint32_t sb = smem_u32(sm);
    int tid = threadIdx.x, l = tid & 31, wid = tid >> 5;
    int wm = wid & 1, wn = wid >> 1;        // 2 x 4 warp grid
    int rowBase = by * 128, colBase = bx * 128;

    float acc[4][4][4];
    #pragma unroll
    for (int mt = 0; mt < 4; mt++)
        #pragma unroll
        for (int nt = 0; nt < 4; nt++)
            #pragma unroll
            for (int e = 0; e < 4; e++) acc[mt][nt][e] = 0.f;

    // ldmatrix per-lane addressing (same pattern for A and B frags)
    int subrow = ((l >> 3) & 1) * 8 + (l & 7);
    int khalfB = (l >> 4) * 16;             // byte offset of k-half

    const uint4* q4[3] = { (const uint4*)g_q0, (const uint4*)g_q1, (const uint4*)g_q2 };

    for (int kk = 0; kk < DIM; kk += 32) {
        __syncthreads();
        int kw = kk >> 3;                   // uint4 column base
        #pragma unroll
        for (int it = 0; it < 2; it++) {
            int idx = tid + it * 256;       // 0..511
            int row = idx >> 2, c = idx & 3;
            int so = row * PADB + c * 16;
            #pragma unroll
            for (int sp = 0; sp < 3; sp++) {
                *(uint4*)(sm + sp * BUFSZ + so) =
                    q4[sp][(size_t)(rowBase + row) * 32 + kw + c];
                *(uint4*)(sm + (3 + sp) * BUFSZ + so) =
                    q4[sp][(size_t)(colBase + row) * 32 + kw + c];
            }
        }
        __syncthreads();
        #pragma unroll
        for (int ks = 0; ks < 2; ks++) {
            int kb = ks * 32 + khalfB;
            // B fragments for all 3 splits: b[split][nt][2]
            uint32_t bf[3][4][2];
            #pragma unroll
            for (int sp = 0; sp < 3; sp++) {
                #pragma unroll
                for (int nt2 = 0; nt2 < 2; nt2++) {
                    uint32_t r0, r1, r2, r3;
                    uint32_t ad = sb + (3 + sp) * BUFSZ
                                + (wn * 32 + nt2 * 16 + subrow) * PADB + kb;
                    ldm_x4(r0, r1, r2, r3, ad);
                    bf[sp][nt2 * 2][0]     = r0; bf[sp][nt2 * 2][1]     = r2;
                    bf[sp][nt2 * 2 + 1][0] = r1; bf[sp][nt2 * 2 + 1][1] = r3;
                }
            }
            #pragma unroll
            for (int mt = 0; mt < 4; mt++) {
                uint32_t a[4];
                uint32_t abase = (wm * 64 + mt * 16 + subrow) * PADB + kb;
                // A0 x {B0, B1, B2}
                ldm_x4(a[0], a[1], a[2], a[3], sb + 0 * BUFSZ + abase);
                #pragma unroll
                for (int nt = 0; nt < 4; nt++) {
                    mma_bf16(acc[mt][nt], a, bf[0][nt]);
                    mma_bf16(acc[mt][nt], a, bf[1][nt]);
                    mma_bf16(acc[mt][nt], a, bf[2][nt]);
                }
                // A1 x {B0, B1}
                ldm_x4(a[0], a[1], a[2], a[3], sb + 1 * BUFSZ + abase);
                #pragma unroll
                for (int nt = 0; nt < 4; nt++) {
                    mma_bf16(acc[mt][nt], a, bf[0][nt]);
                    mma_bf16(acc[mt][nt], a, bf[1][nt]);
                }
                // A2 x {B0}
                ldm_x4(a[0], a[1], a[2], a[3], sb + 2 * BUFSZ + abase);
                #pragma unroll
                for (int nt = 0; nt < 4; nt++)
                    mma_bf16(acc[mt][nt], a, bf[0][nt]);
            }
        }
    }

    // direct store (c frag: rows t/4, t/4+8; cols (t&3)*2, +1)
    int fr = l >> 2, fc = (l & 3) * 2;
    #pragma unroll
    for (int mt = 0; mt < 4; mt++) {
        #pragma unroll
        for (int nt = 0; nt < 4; nt++) {
            size_t r0 = (size_t)(rowBase + wm * 64 + mt * 16 + fr);
            int c0 = colBase + wn * 32 + nt * 8 + fc;
            *(float2*)&g_S[r0 * NQ + c0] = make_float2(acc[mt][nt][0], acc[mt][nt][1]);
            *(float2*)&g_S[(r0 + 8) * NQ + c0] = make_float2(acc[mt][nt][2], acc[mt][nt][3]);
        }
    }

    // mirrored store via smem transpose (coalesced), two 64-col halves
    if (bx != by) {
        float* st = (float*)sm;             // [64][132] floats = 33792 B
        #pragma unroll
        for (int h = 0; h < 2; h++) {
            __syncthreads();
            if ((wn >> 1) == h) {
                #pragma unroll
                for (int mt = 0; mt < 4; mt++) {
                    int lrow = wm * 64 + mt * 16 + fr;
                    #pragma unroll
                    for (int nt = 0; nt < 4; nt++) {
                        int cl = (wn & 1) * 32 + nt * 8 + fc;
                        st[cl * 132 + lrow]           = acc[mt][nt][0];
                        st[(cl + 1) * 132 + lrow]     = acc[mt][nt][1];
                        st[cl * 132 + lrow + 8]       = acc[mt][nt][2];
                        st[(cl + 1) * 132 + lrow + 8] = acc[mt][nt][3];
                    }
                }
            }
            __syncthreads();
            #pragma unroll
            for (int it = 0; it < 8; it++) {
                int idx = tid + it * 256;
                int r = idx >> 5, cq = idx & 31;
                float4 v = *(float4*)&st[r * 132 + cq * 4];
                *(float4*)&g_S[(size_t)(colBase + h * 64 + r) * NQ + rowBase + cq * 4] = v;
            }
        }
    }
}

// ---------------- 6) per-row top-10 ----------------------------------------
__global__ __launch_bounds__(256) void topk_kernel() {
    int i = blockIdx.x, t = threadIdx.x;
    const float* row = g_S + (size_t)i * NQ;

    float tv[KNEIGH]; int ti[KNEIGH];
    #pragma unroll
    for (int c = 0; c < KNEIGH; c++) { tv[c] = -CUDART_INF_F; ti[c] = -1; }

    for (int j = t; j < NQ; j += 256) {
        float s = row[j];
        if (s > tv[KNEIGH - 1]) {
            int jj = j;
            #pragma unroll
            for (int c = 0; c < KNEIGH; c++) {
                if (s > tv[c]) {
                    float pv = tv[c]; int pi = ti[c];
                    tv[c] = s; ti[c] = jj;
                    s = pv; jj = pi;
                }
            }
        }
    }

    __shared__ float cv[256][KNEIGH];
    __shared__ int   ci[256][KNEIGH];
    __shared__ float rv[256];
    __shared__ int   ri[256];
    __shared__ int   rt[256];
    #pragma unroll
    for (int c = 0; c < KNEIGH; c++) { cv[t][c] = tv[c]; ci[t][c] = ti[c]; }
    __syncthreads();

    int p = 0;
    for (int r = 0; r < KNEIGH; r++) {
        rv[t] = (p < KNEIGH) ? cv[t][p] : -CUDART_INF_F;
        ri[t] = (p < KNEIGH) ? ci[t][p] : -1;
        rt[t] = t;
        __syncthreads();
        for (int o = 128; o > 0; o >>= 1) {
            if (t < o) {
                if (rv[t + o] > rv[t]) {
                    rv[t] = rv[t + o]; ri[t] = ri[t + o]; rt[t] = rt[t + o];
                }
            }
            __syncthreads();
        }
        if (t == 0) g_topidx[i * KNEIGH + r] = ri[0];
        int win = rt[0];
        __syncthreads();
        if (t == win) p++;
    }
}

// ---------------- 7) mutual kNN softmax + adapted queries ------------------
__global__ void mutual_kernel() {
    int i = blockIdx.x, t = threadIdx.x;
    __shared__ int   nidx[KNEIGH];
    __shared__ float wgt[KNEIGH];
    if (t < KNEIGH) nidx[t] = g_topidx[i * KNEIGH + t];
    __syncthreads();
    if (t < KNEIGH) {
        int jn = nidx[t];
        bool mut = false;
        #pragma unroll
        for (int c = 0; c < KNEIGH; c++)
            if (g_topidx[jn * KNEIGH + c] == i) mut = true;
        wgt[t] = mut ? g_S[(size_t)i * NQ + jn] : -CUDART_INF_F;
    }
    __syncthreads();
    if (t == 0) {
        float m = -CUDART_INF_F;
        #pragma unroll
        for (int c = 0; c < KNEIGH; c++) if (wgt[c] > m) m = wgt[c];
        float sum = 0.f;
        float e[KNEIGH];
        #pragma unroll
        for (int c = 0; c < KNEIGH; c++) { e[c] = expf(wgt[c] - m); sum += e[c]; }
        float inv = 1.0f / sum;
        #pragma unroll
        for (int c = 0; c < KNEIGH; c++) wgt[c] = e[c] * inv;
    }
    __syncthreads();
    float acc = 0.f;
    #pragma unroll
    for (int c = 0; c < KNEIGH; c++) {
        float w = wgt[c];
        if (w != 0.f) acc += w * g_query[(size_t)nidx[c] * DIM + t];
    }
    g_aq[(size_t)i * DIM + t] = acc;
}

// ---------------- 8) final: tao * cos(adapted_query, adapted_proto) --------
__global__ void final_kernel(const float* __restrict__ tao, float* __restrict__ out) {
    int i = blockIdx.x, t = threadIdx.x;
    __shared__ float sh8[8];
    __shared__ float q[DIM];
    float v = g_aq[(size_t)i * DIM + t];
    float ss = block_reduce_sum_256(v * v, sh8);
    q[t] = v / sqrtf(ss);
    __syncthreads();
    int w = t >> 5, lane = t & 31;
    float tv = tao[0];
    for (int c = w; c < NCLS; c += 8) {
        const float* p = g_apn + c * DIM;
        float s = 0.f;
        #pragma unroll
        for (int u = 0; u < DIM; u += 32) s += q[u + lane] * p[u + lane];
        #pragma unroll
        for (int o = 16; o > 0; o >>= 1) s += __shfl_down_sync(0xffffffffu, s, o);
        if (lane == 0) out[(size_t)i * NCLS + c] = tv * s;
    }
}

// ---------------- launch ----------------------------------------------------
extern "C" void kernel_launch(void* const* d_in, const int* in_sizes, int n_in,
                              void* d_out, int out_size) {
    const float* x   = (const float*)d_in[0];
    const float* tao = (const float*)d_in[1];
    float* out = (float*)d_out;

    cudaFuncSetAttribute(simgemm_mma_kernel,
                         cudaFuncAttributeMaxDynamicSharedMemorySize, GEMM_SMEM);

    proto_kernel<<<NCLS, 256>>>(x);
    qnorm_presim_kernel<<<NQ, 256>>>(x);
    adaptproto_kernel<<<NCLS, 256>>>();
    apnorm_kernel<<<NCLS, 256>>>();
    simgemm_mma_kernel<<<dim3(NQ / 128, NQ / 128), 256, GEMM_SMEM>>>();
    topk_kernel<<<NQ, 256>>>();
    mutual_kernel<<<NQ, 256>>>();
    final_kernel<<<NQ, 256>>>(tao, out);
}

// round 17
// speedup vs baseline: 2.0634x; 1.2398x over previous
#include <cuda_runtime.h>
#include <cuda_fp16.h>
#include <cstdint>
#include <math_constants.h>

// Problem constants
#define NCLS   64
#define KSUP   5
#define QPG    128
#define DIM    256
#define GROUP  (KSUP + QPG)   // 133
#define NQ     (NCLS * QPG)   // 8192
#define KNEIGH 10
#define NTILE  (NQ / 128)     // 64 column tiles

// ---------------- scratch (device globals) ----------------
__device__ float g_query[NQ * DIM];                   // raw queries (8 MB)
__device__ __align__(16) __half g_h0[NQ * DIM];       // fp16 split hi (x*256)
__device__ __align__(16) __half g_h1[NQ * DIM];       // fp16 split lo
__device__ float g_proto[NCLS * DIM];
__device__ float g_pn[NCLS * DIM];
__device__ float g_selfsim[NCLS];
__device__ unsigned g_mbits[NCLS];
__device__ float g_preval[NQ];
__device__ int   g_prelabel[NQ];
__device__ float g_candv[(size_t)NQ * NTILE * KNEIGH];   // 21 MB
__device__ int   g_candi[(size_t)NQ * NTILE * KNEIGH];   // 21 MB
__device__ float g_topval[NQ * KNEIGH];
__device__ int   g_topidx[NQ * KNEIGH];
__device__ float g_ap[NCLS * DIM];
__device__ float g_apn[NCLS * DIM];
__device__ float g_aq[NQ * DIM];

// ---------------- helpers ----------------
__device__ __forceinline__ uint32_t smem_u32(const void* p) {
    uint32_t a;
    asm("{ .reg .u64 t; cvta.to.shared.u64 t, %1; cvt.u32.u64 %0, t; }"
        : "=r"(a) : "l"(p));
    return a;
}
__device__ __forceinline__ void ldm_x4(uint32_t& r0, uint32_t& r1,
                                       uint32_t& r2, uint32_t& r3, uint32_t addr) {
    asm volatile("ldmatrix.sync.aligned.m8n8.x4.shared.b16 {%0,%1,%2,%3}, [%4];"
                 : "=r"(r0), "=r"(r1), "=r"(r2), "=r"(r3) : "r"(addr));
}
__device__ __forceinline__ void mma_f16(float* c, const uint32_t* a, const uint32_t* b) {
    asm volatile(
        "mma.sync.aligned.m16n8k16.row.col.f32.f16.f16.f32 "
        "{%0,%1,%2,%3}, {%4,%5,%6,%7}, {%8,%9}, {%0,%1,%2,%3};"
        : "+f"(c[0]), "+f"(c[1]), "+f"(c[2]), "+f"(c[3])
        : "r"(a[0]), "r"(a[1]), "r"(a[2]), "r"(a[3]), "r"(b[0]), "r"(b[1]));
}

// ordered-uint encode/decode for float atomicMax
__device__ __forceinline__ unsigned fenc(float f) {
    unsigned u = __float_as_uint(f);
    return (u >> 31) ? ~u : (u | 0x80000000u);
}
__device__ __forceinline__ float fdec(unsigned u) {
    return (u & 0x80000000u) ? __uint_as_float(u & 0x7fffffffu) : __uint_as_float(~u);
}

// top-k insertion (static unrolled indices; same pattern as passing kernel)
#define TOPK_INSERT(tv, ti, sval, sidx) do {                                   \
    float _s = (sval); int _j = (sidx);                                        \
    if (_s > tv[KNEIGH - 1]) {                                                 \
        _Pragma("unroll")                                                      \
        for (int _c = 0; _c < KNEIGH; _c++) {                                  \
            if (_s > tv[_c]) {                                                 \
                float _pv = tv[_c]; int _pi = ti[_c];                          \
                tv[_c] = _s; ti[_c] = _j; _s = _pv; _j = _pi;                  \
            }                                                                  \
        }                                                                      \
    }                                                                          \
} while (0)

__device__ __forceinline__ float block_reduce_sum_256(float v, float* sh8) {
    int t = threadIdx.x;
    #pragma unroll
    for (int o = 16; o > 0; o >>= 1) v += __shfl_down_sync(0xffffffffu, v, o);
    if ((t & 31) == 0) sh8[t >> 5] = v;
    __syncthreads();
    if (t < 8) {
        v = sh8[t];
        #pragma unroll
        for (int o = 4; o > 0; o >>= 1) v += __shfl_down_sync(0xffu, v, o);
        if (t == 0) sh8[0] = v;
    }
    __syncthreads();
    float r = sh8[0];
    __syncthreads();
    return r;
}

// ---------------- 1) prototypes ----------------
__global__ void proto_kernel(const float* __restrict__ x) {
    int b = blockIdx.x, t = threadIdx.x;
    __shared__ float sh8[8];
    float s = 0.f;
    #pragma unroll
    for (int i = 0; i < KSUP; i++)
        s += x[(size_t)(b * GROUP + i) * DIM + t];
    float p = s * (1.0f / KSUP);
    g_proto[b * DIM + t] = p;
    float ss = block_reduce_sum_256(p * p, sh8);
    float pn = p / sqrtf(ss);
    g_pn[b * DIM + t] = pn;
    float ss2 = block_reduce_sum_256(pn * pn, sh8);
    if (t == 0) {
        g_selfsim[b] = ss2;
        g_mbits[b] = fenc(-CUDART_INF_F);
    }
}

// ---------------- 2) fused qnorm + fp16 split + presim + class max ---------
__global__ void qnorm_presim_kernel(const float* __restrict__ x) {
    int i = blockIdx.x, t = threadIdx.x;
    int g = i / QPG, qi = i - g * QPG;
    __shared__ float sh8[8];
    __shared__ float q[DIM];
    __shared__ float sims[NCLS];
    float v = x[(size_t)(g * GROUP + KSUP + qi) * DIM + t];
    g_query[(size_t)i * DIM + t] = v;
    float ss = block_reduce_sum_256(v * v, sh8);
    float qn = v / sqrtf(ss);
    q[t] = qn;
    // fp16 two-way split of qn*256 (scaled to avoid fp16 subnormals in h1)
    float qs = qn * 256.0f;
    __half h0 = __float2half_rn(qs);
    float r1 = qs - __half2float(h0);
    __half h1 = __float2half_rn(r1);
    size_t off = (size_t)i * DIM + t;
    g_h0[off] = h0; g_h1[off] = h1;
    __syncthreads();
    int w = t >> 5, lane = t & 31;
    for (int c = w; c < NCLS; c += 8) {
        const float* p = g_pn + c * DIM;
        float s = 0.f;
        #pragma unroll
        for (int u = 0; u < DIM; u += 32) s += q[u + lane] * p[u + lane];
        #pragma unroll
        for (int o = 16; o > 0; o >>= 1) s += __shfl_down_sync(0xffffffffu, s, o);
        if (lane == 0) sims[c] = s;
    }
    __syncthreads();
    if (t == 0) {
        float best = -CUDART_INF_F; int bi = 0;
        #pragma unroll
        for (int c = 0; c < NCLS; c++)
            if (sims[c] > best) { best = sims[c]; bi = c; }
        g_preval[i] = best;
        g_prelabel[i] = bi;
        atomicMax(&g_mbits[bi], fenc(best));
    }
}

// ---------------- 3) adapted prototypes (warp-parallel ballot scan) --------
__global__ void adaptproto_kernel() {
    int j = blockIdx.x, t = threadIdx.x;
    int w = t >> 5, l = t & 31;
    __shared__ float sacc[8][DIM];
    __shared__ float sz[8];
    float m = fmaxf(fdec(g_mbits[j]), g_selfsim[j]);
    float acc[8];
    #pragma unroll
    for (int jj = 0; jj < 8; jj++) acc[jj] = 0.f;
    float z = 0.f;
    int base0 = w * (NQ / 8);
    for (int base = base0; base < base0 + NQ / 8; base += 32) {
        int i = base + l;
        int lab = g_prelabel[i];
        float pv = g_preval[i];
        unsigned mask = __ballot_sync(0xffffffffu, lab == j);
        while (mask) {
            int b = __ffs(mask) - 1;
            mask &= mask - 1;
            int ib = base + b;
            float wv = __shfl_sync(0xffffffffu, pv, b);
            float e = expf(wv - m);
            if (l == 0) z += e;
            const float* row = g_query + (size_t)ib * DIM;
            #pragma unroll
            for (int jj = 0; jj < 8; jj++) acc[jj] += e * row[l + 32 * jj];
        }
    }
    #pragma unroll
    for (int jj = 0; jj < 8; jj++) sacc[w][l + 32 * jj] = acc[jj];
    if (l == 0) sz[w] = z;
    __syncthreads();
    float a = 0.f, Z = 0.f;
    #pragma unroll
    for (int ww = 0; ww < 8; ww++) { a += sacc[ww][t]; Z += sz[ww]; }
    float es = expf(g_selfsim[j] - m);
    Z += es;
    g_ap[j * DIM + t] = (a + es * g_proto[j * DIM + t]) / Z;
}

// ---------------- 4) normalize adapted protos ------------------------------
__global__ void apnorm_kernel() {
    int j = blockIdx.x, t = threadIdx.x;
    __shared__ float sh8[8];
    float v = g_ap[j * DIM + t];
    float ss = block_reduce_sum_256(v * v, sh8);
    g_apn[j * DIM + t] = v / sqrtf(ss);
}

// ---------------- 5) GEMM + fused per-tile top-k ---------------------------
// 128x128 CTA tile, 8 warps (2m x 4n), fp16 2-split, 3 passes (00,01,10).
// Epilogue stages tile halves to smem and emits per-(row, coltile) top-10
// candidates for both orientations (normal + mirror). No S matrix.
#define PADB  80
#define BUFSZ (128 * PADB)                    // 10240 B per operand buffer
#define ST_STRIDE 129
#define ST_BYTES  (64 * ST_STRIDE * 4)        // 33024
#define LV_OFF    ST_BYTES
#define LI_OFF    (ST_BYTES + 10240)
#define GEMM_SMEM (ST_BYTES + 20480)          // 53504 > 4*BUFSZ=40960

__global__ __launch_bounds__(256, 2) void simgemm_mma_kernel() {
    int bx = blockIdx.x, by = blockIdx.y;
    if (by > bx) return;                      // symmetric: upper triangle only
    extern __shared__ __align__(16) char sm[];
    uint32_t sb = smem_u32(sm);
    int tid = threadIdx.x, l = tid & 31, wid = tid >> 5;
    int wm = wid & 1, wn = wid >> 1;
    int rowBase = by * 128, colBase = bx * 128;

    float acc[4][4][4];
    #pragma unroll
    for (int mt = 0; mt < 4; mt++)
        #pragma unroll
        for (int nt = 0; nt < 4; nt++)
            #pragma unroll
            for (int e = 0; e < 4; e++) acc[mt][nt][e] = 0.f;

    int subrow = ((l >> 3) & 1) * 8 + (l & 7);
    int khalfB = (l >> 4) * 16;

    const uint4* q4[2] = { (const uint4*)g_h0, (const uint4*)g_h1 };

    for (int kk = 0; kk < DIM; kk += 32) {
        __syncthreads();
        int kw = kk >> 3;
        #pragma unroll
        for (int it = 0; it < 2; it++) {
            int idx = tid + it * 256;
            int row = idx >> 2, c = idx & 3;
            int so = row * PADB + c * 16;
            #pragma unroll
            for (int sp = 0; sp < 2; sp++) {
                *(uint4*)(sm + sp * BUFSZ + so) =
                    q4[sp][(size_t)(rowBase + row) * 32 + kw + c];
                *(uint4*)(sm + (2 + sp) * BUFSZ + so) =
                    q4[sp][(size_t)(colBase + row) * 32 + kw + c];
            }
        }
        __syncthreads();
        #pragma unroll
        for (int ks = 0; ks < 2; ks++) {
            int kb = ks * 32 + khalfB;
            uint32_t bf[2][4][2];
            #pragma unroll
            for (int sp = 0; sp < 2; sp++) {
                #pragma unroll
                for (int nt2 = 0; nt2 < 2; nt2++) {
                    uint32_t r0, r1, r2, r3;
                    uint32_t ad = sb + (2 + sp) * BUFSZ
                                + (wn * 32 + nt2 * 16 + subrow) * PADB + kb;
                    ldm_x4(r0, r1, r2, r3, ad);
                    bf[sp][nt2 * 2][0]     = r0; bf[sp][nt2 * 2][1]     = r2;
                    bf[sp][nt2 * 2 + 1][0] = r1; bf[sp][nt2 * 2 + 1][1] = r3;
                }
            }
            #pragma unroll
            for (int mt = 0; mt < 4; mt++) {
                uint32_t a[4];
                uint32_t abase = (wm * 64 + mt * 16 + subrow) * PADB + kb;
                // A0 x {B0, B1}
                ldm_x4(a[0], a[1], a[2], a[3], sb + 0 * BUFSZ + abase);
                #pragma unroll
                for (int nt = 0; nt < 4; nt++) {
                    mma_f16(acc[mt][nt], a, bf[0][nt]);
                    mma_f16(acc[mt][nt], a, bf[1][nt]);
                }
                // A1 x {B0}
                ldm_x4(a[0], a[1], a[2], a[3], sb + 1 * BUFSZ + abase);
                #pragma unroll
                for (int nt = 0; nt < 4; nt++)
                    mma_f16(acc[mt][nt], a, bf[0][nt]);
            }
        }
    }

    // ---- fused epilogue: per-tile top-10 candidates ----
    const float SCL = 1.0f / 65536.0f;        // undo the 256x input scaling
    float* st = (float*)sm;                   // [64][129]
    float* lv = (float*)(sm + LV_OFF);        // sorted-list values (reused)
    int*   li = (int*)(sm + LI_OFF);          // sorted-list indices
    int fr = l >> 2, fc = (l & 3) * 2;
    int r4 = tid >> 2, part = tid & 3;
    int ccol = tid >> 1, seg = tid & 1;

    // mirror-orientation running top-k (per column, across both halves)
    float ctv[KNEIGH]; int cti[KNEIGH];
    #pragma unroll
    for (int c = 0; c < KNEIGH; c++) { ctv[c] = -CUDART_INF_F; cti[c] = 0; }

    for (int h = 0; h < 2; h++) {
        __syncthreads();
        if (wm == h) {
            #pragma unroll
            for (int mt = 0; mt < 4; mt++) {
                int lr = mt * 16 + fr;
                #pragma unroll
                for (int nt = 0; nt < 4; nt++) {
                    int c0 = wn * 32 + nt * 8 + fc;
                    st[lr * ST_STRIDE + c0]           = acc[mt][nt][0] * SCL;
                    st[lr * ST_STRIDE + c0 + 1]       = acc[mt][nt][1] * SCL;
                    st[(lr + 8) * ST_STRIDE + c0]     = acc[mt][nt][2] * SCL;
                    st[(lr + 8) * ST_STRIDE + c0 + 1] = acc[mt][nt][3] * SCL;
                }
            }
        }
        __syncthreads();
        // row-orientation: 4 threads/row, 32 cols each (bank-staggered)
        {
            float tv[KNEIGH]; int ti[KNEIGH];
            #pragma unroll
            for (int c = 0; c < KNEIGH; c++) { tv[c] = -CUDART_INF_F; ti[c] = 0; }
            #pragma unroll
            for (int cc = 0; cc < 32; cc++) {
                int c = part * 32 + ((cc + part * 8) & 31);
                TOPK_INSERT(tv, ti, st[r4 * ST_STRIDE + c], colBase + c);
            }
            #pragma unroll
            for (int s = 0; s < KNEIGH; s++) {
                lv[(r4 * 4 + part) * KNEIGH + s] = tv[s];
                li[(r4 * 4 + part) * KNEIGH + s] = ti[s];
            }
        }
        __syncthreads();
        if (part == 0) {                      // 4-way merge of sorted lists
            int p0 = 0, p1 = 0, p2 = 0, p3 = 0;
            size_t ob = ((size_t)(rowBase + h * 64 + r4) * NTILE + bx) * KNEIGH;
            #pragma unroll
            for (int s = 0; s < KNEIGH; s++) {
                float v0 = lv[(r4 * 4 + 0) * KNEIGH + p0];
                float v1 = lv[(r4 * 4 + 1) * KNEIGH + p1];
                float v2 = lv[(r4 * 4 + 2) * KNEIGH + p2];
                float v3 = lv[(r4 * 4 + 3) * KNEIGH + p3];
                float best = v0; int bl = 0;
                if (v1 > best) { best = v1; bl = 1; }
                if (v2 > best) { best = v2; bl = 2; }
                if (v3 > best) { best = v3; bl = 3; }
                int pp = (bl == 0) ? p0 : (bl == 1) ? p1 : (bl == 2) ? p2 : p3;
                g_candv[ob + s] = best;
                g_candi[ob + s] = li[(r4 * 4 + bl) * KNEIGH + pp];
                if (bl == 0) p0++; else if (bl == 1) p1++;
                else if (bl == 2) p2++; else p3++;
            }
        }
        // mirror orientation: 2 threads/col, 32 rows each (registers only)
        if (bx != by) {
            #pragma unroll
            for (int rr = 0; rr < 32; rr++) {
                int lrow = seg * 32 + ((rr + seg * 16) & 31);
                TOPK_INSERT(ctv, cti, st[lrow * ST_STRIDE + ccol],
                            rowBase + h * 64 + lrow);
            }
        }
    }
    if (bx != by) {
        __syncthreads();
        #pragma unroll
        for (int s = 0; s < KNEIGH; s++) {
            lv[(ccol * 2 + seg) * KNEIGH + s] = ctv[s];
            li[(ccol * 2 + seg) * KNEIGH + s] = cti[s];
        }
        __syncthreads();
        if (seg == 0) {
            int pa = 0, pb = 0;
            size_t ob = ((size_t)(colBase + ccol) * NTILE + by) * KNEIGH;
            #pragma unroll
            for (int s = 0; s < KNEIGH; s++) {
                float va = lv[(ccol * 2) * KNEIGH + pa];
                float vb = lv[(ccol * 2 + 1) * KNEIGH + pb];
                if (va >= vb) {
                    g_candv[ob + s] = va;
                    g_candi[ob + s] = li[(ccol * 2) * KNEIGH + pa]; pa++;
                } else {
                    g_candv[ob + s] = vb;
                    g_candi[ob + s] = li[(ccol * 2 + 1) * KNEIGH + pb]; pb++;
                }
            }
        }
    }
}

// ---------------- 6) merge 64 per-tile candidate lists → global top-10 -----
__global__ __launch_bounds__(64) void merge_topk_kernel() {
    int i = blockIdx.x, t = threadIdx.x;      // 64 threads, one per coltile
    __shared__ float sv[NTILE * KNEIGH];
    __shared__ int   si[NTILE * KNEIGH];
    size_t gb = ((size_t)i * NTILE + t) * KNEIGH;
    #pragma unroll
    for (int s = 0; s < KNEIGH; s++) {
        sv[t * KNEIGH + s] = g_candv[gb + s];
        si[t * KNEIGH + s] = g_candi[gb + s];
    }
    __syncthreads();
    for (int step = 1; step < NTILE; step <<= 1) {
        if ((t & (2 * step - 1)) == 0) {
            float mv[KNEIGH]; int mi[KNEIGH];
            int pa = 0, pb = 0;
            int A = t * KNEIGH, B = (t + step) * KNEIGH;
            #pragma unroll
            for (int s = 0; s < KNEIGH; s++) {
                float va = sv[A + pa], vb = sv[B + pb];
                if (va >= vb) { mv[s] = va; mi[s] = si[A + pa]; pa++; }
                else          { mv[s] = vb; mi[s] = si[B + pb]; pb++; }
            }
            #pragma unroll
            for (int s = 0; s < KNEIGH; s++) { sv[A + s] = mv[s]; si[A + s] = mi[s]; }
        }
        __syncthreads();
    }
    if (t < KNEIGH) {
        g_topval[i * KNEIGH + t] = sv[t];
        g_topidx[i * KNEIGH + t] = si[t];
    }
}

// ---------------- 7) mutual kNN softmax + adapted queries ------------------
__global__ void mutual_kernel() {
    int i = blockIdx.x, t = threadIdx.x;
    __shared__ int   nidx[KNEIGH];
    __shared__ float wgt[KNEIGH];
    if (t < KNEIGH) nidx[t] = g_topidx[i * KNEIGH + t];
    __syncthreads();
    if (t < KNEIGH) {
        int jn = nidx[t];
        bool mut = false;
        #pragma unroll
        for (int c = 0; c < KNEIGH; c++)
            if (g_topidx[jn * KNEIGH + c] == i) mut = true;
        wgt[t] = mut ? g_topval[i * KNEIGH + t] : -CUDART_INF_F;
    }
    __syncthreads();
    if (t == 0) {
        float m = -CUDART_INF_F;
        #pragma unroll
        for (int c = 0; c < KNEIGH; c++) if (wgt[c] > m) m = wgt[c];
        float sum = 0.f;
        float e[KNEIGH];
        #pragma unroll
        for (int c = 0; c < KNEIGH; c++) { e[c] = expf(wgt[c] - m); sum += e[c]; }
        float inv = 1.0f / sum;
        #pragma unroll
        for (int c = 0; c < KNEIGH; c++) wgt[c] = e[c] * inv;
    }
    __syncthreads();
    float acc = 0.f;
    #pragma unroll
    for (int c = 0; c < KNEIGH; c++) {
        float w = wgt[c];
        if (w != 0.f) acc += w * g_query[(size_t)nidx[c] * DIM + t];
    }
    g_aq[(size_t)i * DIM + t] = acc;
}

// ---------------- 8) final: tao * cos(adapted_query, adapted_proto) --------
__global__ void final_kernel(const float* __restrict__ tao, float* __restrict__ out) {
    int i = blockIdx.x, t = threadIdx.x;
    __shared__ float sh8[8];
    __shared__ float q[DIM];
    float v = g_aq[(size_t)i * DIM + t];
    float ss = block_reduce_sum_256(v * v, sh8);
    q[t] = v / sqrtf(ss);
    __syncthreads();
    int w = t >> 5, lane = t & 31;
    float tv = tao[0];
    for (int c = w; c < NCLS; c += 8) {
        const float* p = g_apn + c * DIM;
        float s = 0.f;
        #pragma unroll
        for (int u = 0; u < DIM; u += 32) s += q[u + lane] * p[u + lane];
        #pragma unroll
        for (int o = 16; o > 0; o >>= 1) s += __shfl_down_sync(0xffffffffu, s, o);
        if (lane == 0) out[(size_t)i * NCLS + c] = tv * s;
    }
}

// ---------------- launch ----------------------------------------------------
extern "C" void kernel_launch(void* const* d_in, const int* in_sizes, int n_in,
                              void* d_out, int out_size) {
    const float* x   = (const float*)d_in[0];
    const float* tao = (const float*)d_in[1];
    float* out = (float*)d_out;

    cudaFuncSetAttribute(simgemm_mma_kernel,
                         cudaFuncAttributeMaxDynamicSharedMemorySize, GEMM_SMEM);

    proto_kernel<<<NCLS, 256>>>(x);
    qnorm_presim_kernel<<<NQ, 256>>>(x);
    adaptproto_kernel<<<NCLS, 256>>>();
    apnorm_kernel<<<NCLS, 256>>>();
    simgemm_mma_kernel<<<dim3(NQ / 128, NQ / 128), 256, GEMM_SMEM>>>();
    merge_topk_kernel<<<NQ, 64>>>();
    mutual_kernel<<<NQ, 256>>>();
    final_kernel<<<NQ, 256>>>(tao, out);
}